// round 3
// baseline (speedup 1.0000x reference)
#include <cuda_runtime.h>

// PowerLinear, fully fused single persistent kernel.
//   c = colsum(R);  W[b,j] = (n_b==0) ? (c.x_b) : d_j^{n_b} * c_j * x[b,j]
//   y[b,i] = sum_j W[b,j] * R[i,j]
// Inputs: x [64,1024] f32, n [64] i32, diag [1024] f32, rot [1024,1024] f32
// Output: [64,1024] f32

#define BB 64
#define DD 1024
#define NBLK 128
#define NTHR 256
#define KSPLIT 8
#define ITILES 16          // 16 x 64-col output tiles
#define KC 16              // k per smem stage
#define NSTAGE 8           // 128 / 16

typedef unsigned long long u64;

__device__ float g_cp[NBLK * DD];        // colsum partials [p][j]
__device__ float g_cxpT[BB * NBLK];      // cx partials [b][t]
__device__ float g_W[DD * BB];           // W transposed [j][b]
__device__ float g_part[KSPLIT * BB * DD];
__device__ unsigned g_bar;

__device__ __forceinline__ void gbar()
{
    __syncthreads();
    if (threadIdx.x == 0) {
        __threadfence();
        unsigned v = atomicAdd(&g_bar, 1u);
        unsigned target = (v & ~(unsigned)(NBLK - 1)) + NBLK;
        for (;;) {
            unsigned cur;
            asm volatile("ld.global.acquire.gpu.u32 %0, [%1];"
                         : "=r"(cur) : "l"(&g_bar));
            if ((int)(cur - target) >= 0) break;
            __nanosleep(64);
        }
    }
    __syncthreads();
}

__device__ __forceinline__ u64 pk2(float lo, float hi)
{
    u64 r;
    asm("mov.b64 %0, {%1,%2};" : "=l"(r) : "f"(lo), "f"(hi));
    return r;
}
__device__ __forceinline__ void upk2(u64 v, float& lo, float& hi)
{
    asm("mov.b64 {%0,%1}, %2;" : "=f"(lo), "=f"(hi) : "l"(v));
}
__device__ __forceinline__ void fma2(u64& d, u64 a, u64 b)
{
    asm("fma.rn.f32x2 %0, %1, %2, %0;" : "+l"(d) : "l"(a), "l"(b));
}

__global__ __launch_bounds__(NTHR, 1)
void powerlinear_fused(const float* __restrict__ x,
                       const int*   __restrict__ n,
                       const float* __restrict__ diag,
                       const float* __restrict__ R,
                       float*       __restrict__ out)
{
    // GEMM smem (also reused area is disjoint from phase-1.5 needs)
    __shared__ u64   sRd[2][KC][80];   // padded: element i at index i + (i>>2)
    __shared__ float sW[2][KC][64];
    __shared__ float sm_cx[BB];
    __shared__ int   sm_n0[BB];
    __shared__ float sm_c[8];

    const int tid = threadIdx.x;
    const int bid = blockIdx.x;

    // ---------------- P1: colsum partials (8 R-rows per block) -------------
    {
        const float* rp = R + (bid * 8) * DD + tid * 4;
        float4 a = make_float4(0.f, 0.f, 0.f, 0.f);
#pragma unroll
        for (int r = 0; r < 8; r++) {
            float4 v = *(const float4*)(rp + r * DD);
            a.x += v.x; a.y += v.y; a.z += v.z; a.w += v.w;
        }
        *(float4*)(g_cp + bid * DD + tid * 4) = a;
    }
    gbar();

    // ---------------- P1.5: c for 8-col tile, cx partials, W ---------------
    {
        const int jj   = tid >> 5;          // 0..7
        const int lane = tid & 31;
        const int j    = bid * 8 + jj;
        float s = 0.f;
#pragma unroll
        for (int q = 0; q < 4; q++)
            s += g_cp[(lane + 32 * q) * DD + j];
#pragma unroll
        for (int off = 16; off > 0; off >>= 1)
            s += __shfl_down_sync(0xffffffffu, s, off);
        if (lane == 0) sm_c[jj] = s;
        __syncthreads();

        if (tid < BB) {
            const int b  = tid;
            const int nb = n[b];
            float xs[8];
            float4 xa = *(const float4*)(x + b * DD + bid * 8);
            float4 xb = *(const float4*)(x + b * DD + bid * 8 + 4);
            xs[0] = xa.x; xs[1] = xa.y; xs[2] = xa.z; xs[3] = xa.w;
            xs[4] = xb.x; xs[5] = xb.y; xs[6] = xb.z; xs[7] = xb.w;

            float cx = 0.f;
#pragma unroll
            for (int q = 0; q < 8; q++) cx = fmaf(sm_c[q], xs[q], cx);
            g_cxpT[b * NBLK + bid] = cx;

#pragma unroll
            for (int q = 0; q < 8; q++) {
                const float dj = diag[bid * 8 + q];
                float p = 1.f;
#pragma unroll
                for (int k = 0; k < 5; k++) p *= (k < nb) ? dj : 1.f;
                g_W[(bid * 8 + q) * BB + b] = sm_c[q] * xs[q] * p;
            }
        }
    }
    gbar();

    // ---------------- P2 prologue: reduce cx, load n flags ------------------
    {
        if (tid < BB) {
            const float4* pp = (const float4*)(g_cxpT + tid * NBLK);
            float s = 0.f;
#pragma unroll
            for (int q = 0; q < NBLK / 4; q++) {
                float4 v = pp[q];
                s += v.x; s += v.y; s += v.z; s += v.w;
            }
            sm_cx[tid] = s;
            sm_n0[tid] = (n[tid] == 0);
        }
        __syncthreads();
    }

    // ---------------- P2: split-K GEMM with f32x2 ---------------------------
    {
        const int it = bid >> 3;            // 0..15
        const int ks = bid & 7;             // 0..7
        const int i0 = it * 64;
        const int k0 = ks * 128;

        const int tx = tid & 15;            // i quad
        const int ty = tid >> 4;            // b quad
        const int i4 = tx * 4;
        const int b4 = ty * 4;
        const int rbase = 5 * tx;           // padded sRd index base (i4 + tx)

        // loader indices
        const int li = tid >> 2;            // 0..63  (R row within tile)
        const int lk = (tid & 3) * 4;       // 0,4,8,12
        const int lpos = li + (li >> 2);    // padded store index

        u64 acc[2][4];
#pragma unroll
        for (int p = 0; p < 2; p++)
#pragma unroll
            for (int c = 0; c < 4; c++) acc[p][c] = 0ull;

        float4 wr = *(const float4*)(g_W + k0 * BB + tid * 4);
        float4 rr = *(const float4*)(R + (i0 + li) * DD + k0 + lk);

        int buf = 0;
#pragma unroll
        for (int s = 0; s < NSTAGE; s++) {
            // store W (with n==0 override)
            {
                const int fi = tid * 4;
                float wv[4] = {wr.x, wr.y, wr.z, wr.w};
#pragma unroll
                for (int c = 0; c < 4; c++) {
                    const int b = (fi + c) & 63;
                    float v = sm_n0[b] ? sm_cx[b] : wv[c];
                    sW[buf][(fi + c) >> 6][b] = v;
                }
            }
            // store R duplicated
            {
                float rv[4] = {rr.x, rr.y, rr.z, rr.w};
#pragma unroll
                for (int c = 0; c < 4; c++)
                    sRd[buf][lk + c][lpos] = pk2(rv[c], rv[c]);
            }
            __syncthreads();

            if (s + 1 < NSTAGE) {
                const int kb = k0 + (s + 1) * KC;
                wr = *(const float4*)(g_W + kb * BB + tid * 4);
                rr = *(const float4*)(R + (i0 + li) * DD + kb + lk);
            }

#pragma unroll
            for (int kk = 0; kk < KC; kk++) {
                u64 w0 = *(const u64*)&sW[buf][kk][b4];
                u64 w1 = *(const u64*)&sW[buf][kk][b4 + 2];
                u64 r0 = sRd[buf][kk][rbase + 0];
                u64 r1 = sRd[buf][kk][rbase + 1];
                u64 r2 = sRd[buf][kk][rbase + 2];
                u64 r3 = sRd[buf][kk][rbase + 3];
                fma2(acc[0][0], w0, r0);
                fma2(acc[0][1], w0, r1);
                fma2(acc[0][2], w0, r2);
                fma2(acc[0][3], w0, r3);
                fma2(acc[1][0], w1, r0);
                fma2(acc[1][1], w1, r1);
                fma2(acc[1][2], w1, r2);
                fma2(acc[1][3], w1, r3);
            }
            buf ^= 1;
        }

        // epilogue: write split-K partials
        float* o = g_part + ks * (BB * DD);
#pragma unroll
        for (int p = 0; p < 2; p++) {
            float lo[4], hi[4];
#pragma unroll
            for (int c = 0; c < 4; c++) upk2(acc[p][c], lo[c], hi[c]);
            const int b = b4 + 2 * p;
            *(float4*)(o + b * DD + i0 + i4) =
                make_float4(lo[0], lo[1], lo[2], lo[3]);
            *(float4*)(o + (b + 1) * DD + i0 + i4) =
                make_float4(hi[0], hi[1], hi[2], hi[3]);
        }
    }
    gbar();

    // ---------------- P3: reduce split-K partials -> out --------------------
    {
        const int idx = bid * 512 + tid * 2;
        float2 s = make_float2(0.f, 0.f);
#pragma unroll
        for (int q = 0; q < KSPLIT; q++) {
            float2 v = *(const float2*)(g_part + q * (BB * DD) + idx);
            s.x += v.x; s.y += v.y;
        }
        *(float2*)(out + idx) = s;
    }
}

extern "C" void kernel_launch(void* const* d_in, const int* in_sizes, int n_in,
                              void* d_out, int out_size)
{
    const float* x    = (const float*)d_in[0];
    const int*   nn   = (const int*)  d_in[1];
    const float* diag = (const float*)d_in[2];
    const float* rot  = (const float*)d_in[3];
    float* out = (float*)d_out;

    powerlinear_fused<<<NBLK, NTHR>>>(x, nn, diag, rot, out);
}

// round 4
// speedup vs baseline: 1.1743x; 1.1743x over previous
#include <cuda_runtime.h>

// PowerLinear:
//   c = colsum(R), rs = rowsum(R)
//   n_b == 0 : y_b = (c . x_b) * rs
//   n_b >= 1 : y_b = R @ ( d^{n_b} * c * x_b )
// Inputs: x [64,1024] f32, n [64] i32, diag [1024] f32, rot [1024,1024] f32
// Output: [64,1024] f32

#define BB 64
#define DD 1024
#define NBLK 128
#define NTHR 256
#define KSPLIT 8
#define KC 16
#define NSTAGE 8           // 128 / 16
#define PAD 68

__device__ float g_cp[NBLK * DD];     // colsum partials [blk][j]
__device__ float g_rs[DD];            // rowsums
__device__ float g_cxpT[BB * NBLK];   // cx partials [b][blk]
__device__ float g_W[DD * BB];        // W transposed [j][b]
__device__ unsigned g_bar;

__device__ __forceinline__ void stcg(float* p, float v)
{
    asm volatile("st.global.cg.f32 [%0], %1;" :: "l"(p), "f"(v) : "memory");
}
__device__ __forceinline__ void redadd(float* p, float v)
{
    asm volatile("red.global.add.f32 [%0], %1;" :: "l"(p), "f"(v) : "memory");
}

// ---------------------------------------------------------------------------
// K1: colsum partials + exact rowsums (8 rows per block) + zero out
// ---------------------------------------------------------------------------
__global__ __launch_bounds__(NTHR) void prep_kernel(const float* __restrict__ R,
                                                    float* __restrict__ out)
{
    const int bid = blockIdx.x;
    const int tid = threadIdx.x;

    const float* rp = R + (bid * 8) * DD + tid * 4;
    float4 a = make_float4(0.f, 0.f, 0.f, 0.f);
    float rs[8];
#pragma unroll
    for (int r = 0; r < 8; r++) {
        float4 v = *(const float4*)(rp + r * DD);
        a.x += v.x; a.y += v.y; a.z += v.z; a.w += v.w;
        rs[r] = (v.x + v.y) + (v.z + v.w);
    }
    *(float4*)(g_cp + bid * DD + tid * 4) = a;

    __shared__ float srs[8][NTHR];
#pragma unroll
    for (int r = 0; r < 8; r++) srs[r][tid] = rs[r];
    __syncthreads();
#pragma unroll
    for (int off = 128; off > 0; off >>= 1) {
        if (tid < off) {
#pragma unroll
            for (int r = 0; r < 8; r++) srs[r][tid] += srs[r][tid + off];
        }
        __syncthreads();
    }
    if (tid < 8) g_rs[bid * 8 + tid] = srs[tid][0];

    // zero output (64*1024 floats / 128 blocks = 512 per block)
    *(float2*)(out + bid * 512 + tid * 2) = make_float2(0.f, 0.f);
}

// ---------------------------------------------------------------------------
// K2: phase A (c, cx partials, W) -> grid barrier -> split-K GEMM + atomics
// ---------------------------------------------------------------------------
__global__ __launch_bounds__(NTHR, 1)
void main_kernel(const float* __restrict__ x,
                 const int*   __restrict__ n,
                 const float* __restrict__ diag,
                 const float* __restrict__ R,
                 float*       __restrict__ out)
{
    __shared__ __align__(16) float sW[2][KC][64];
    __shared__ __align__(16) float sB[2][KC][PAD];
    __shared__ float sm_c[8];
    __shared__ float sm_cx[BB];
    __shared__ float sm_rs[64];
    __shared__ int   sm_n0[BB];

    const int bid = blockIdx.x;
    const int tid = threadIdx.x;

    // ------------- Phase A: j-slice [8*bid, 8*bid+8) -----------------------
    {
        const int jj   = tid >> 5;
        const int lane = tid & 31;
        const int j    = bid * 8 + jj;
        float s = 0.f;
#pragma unroll
        for (int q = 0; q < 4; q++)
            s += g_cp[(lane + 32 * q) * DD + j];
#pragma unroll
        for (int off = 16; off > 0; off >>= 1)
            s += __shfl_down_sync(0xffffffffu, s, off);
        if (lane == 0) sm_c[jj] = s;
        __syncthreads();

        if (tid < BB) {
            const int b  = tid;
            const int nb = n[b];
            float4 xa = *(const float4*)(x + b * DD + bid * 8);
            float4 xb = *(const float4*)(x + b * DD + bid * 8 + 4);
            float xs[8] = {xa.x, xa.y, xa.z, xa.w, xb.x, xb.y, xb.z, xb.w};

            float cx = 0.f;
#pragma unroll
            for (int q = 0; q < 8; q++) cx = fmaf(sm_c[q], xs[q], cx);
            stcg(g_cxpT + b * NBLK + bid, cx);

#pragma unroll
            for (int q = 0; q < 8; q++) {
                const float dj = diag[bid * 8 + q];
                float p = 1.f;
#pragma unroll
                for (int k = 0; k < 5; k++) p *= (k < nb) ? dj : 1.f;
                float w = (nb == 0) ? 0.f : sm_c[q] * xs[q] * p;
                stcg(g_W + (bid * 8 + q) * BB + b, w);
            }
        }
    }

    // ------------- grid barrier --------------------------------------------
    __threadfence();
    __syncthreads();
    if (tid == 0) {
        unsigned v = atomicAdd(&g_bar, 1u);
        unsigned target = (v & ~(unsigned)(NBLK - 1)) + NBLK;
        for (;;) {
            unsigned cur;
            asm volatile("ld.global.acquire.gpu.u32 %0, [%1];"
                         : "=r"(cur) : "l"(&g_bar));
            if ((int)(cur - target) >= 0) break;
            __nanosleep(64);
        }
    }
    __syncthreads();

    // ------------- Phase B: split-K GEMM + atomic epilogue ------------------
    {
        const int it = bid >> 3;
        const int ks = bid & 7;
        const int i0 = it * 64;
        const int k0 = ks * 128;

        // prologue: reduce cx, flags, rowsum tile
        if (tid < BB) {
            const float4* pp = (const float4*)(g_cxpT + tid * NBLK);
            float s = 0.f;
#pragma unroll
            for (int q = 0; q < NBLK / 4; q++) {
                float4 v = __ldcg(pp + q);
                s += (v.x + v.y) + (v.z + v.w);
            }
            sm_cx[tid] = s;
            sm_n0[tid] = (n[tid] == 0);
            sm_rs[tid] = g_rs[i0 + tid];
        }
        __syncthreads();

        const int tx = tid & 15;
        const int ty = tid >> 4;

        // W loader: [k][b]
        const int wk = tid >> 4;            // 0..15
        const int wb = (tid & 15) * 4;
        // R loader (transpose into sB)
        const int li = tid >> 2;            // 0..63
        const int lk = (tid & 3) * 4;

        float acc[4][4];
#pragma unroll
        for (int r = 0; r < 4; r++)
#pragma unroll
            for (int c = 0; c < 4; c++) acc[r][c] = 0.f;

        float4 wr = __ldcg((const float4*)(g_W + (k0 + wk) * BB + wb));
        float4 rr = *(const float4*)(R + (i0 + li) * DD + k0 + lk);

        int buf = 0;
#pragma unroll
        for (int s = 0; s < NSTAGE; s++) {
            *(float4*)&sW[buf][wk][wb] = wr;
            sB[buf][lk + 0][li] = rr.x;
            sB[buf][lk + 1][li] = rr.y;
            sB[buf][lk + 2][li] = rr.z;
            sB[buf][lk + 3][li] = rr.w;
            __syncthreads();

            if (s + 1 < NSTAGE) {
                const int kb = k0 + (s + 1) * KC;
                wr = __ldcg((const float4*)(g_W + (kb + wk) * BB + wb));
                rr = *(const float4*)(R + (i0 + li) * DD + kb + lk);
            }

#pragma unroll
            for (int kk = 0; kk < KC; kk++) {
                const float4 av = *(const float4*)&sW[buf][kk][ty * 4];
                const float4 bv = *(const float4*)&sB[buf][kk][tx * 4];
                acc[0][0] = fmaf(av.x, bv.x, acc[0][0]);
                acc[0][1] = fmaf(av.x, bv.y, acc[0][1]);
                acc[0][2] = fmaf(av.x, bv.z, acc[0][2]);
                acc[0][3] = fmaf(av.x, bv.w, acc[0][3]);
                acc[1][0] = fmaf(av.y, bv.x, acc[1][0]);
                acc[1][1] = fmaf(av.y, bv.y, acc[1][1]);
                acc[1][2] = fmaf(av.y, bv.z, acc[1][2]);
                acc[1][3] = fmaf(av.y, bv.w, acc[1][3]);
                acc[2][0] = fmaf(av.z, bv.x, acc[2][0]);
                acc[2][1] = fmaf(av.z, bv.y, acc[2][1]);
                acc[2][2] = fmaf(av.z, bv.z, acc[2][2]);
                acc[2][3] = fmaf(av.z, bv.w, acc[2][3]);
                acc[3][0] = fmaf(av.w, bv.x, acc[3][0]);
                acc[3][1] = fmaf(av.w, bv.y, acc[3][1]);
                acc[3][2] = fmaf(av.w, bv.z, acc[3][2]);
                acc[3][3] = fmaf(av.w, bv.w, acc[3][3]);
            }
            buf ^= 1;
        }

        // epilogue: atomic add into out; ks==0 also adds the n==0 rank-1 term
#pragma unroll
        for (int r = 0; r < 4; r++) {
            const int b = ty * 4 + r;
            const float extra = (ks == 0 && sm_n0[b]) ? sm_cx[b] : 0.f;
#pragma unroll
            for (int c = 0; c < 4; c++) {
                const int i = tx * 4 + c;
                float v = acc[r][c] + extra * sm_rs[i];
                redadd(out + b * DD + i0 + i, v);
            }
        }
    }
}

// ---------------------------------------------------------------------------
extern "C" void kernel_launch(void* const* d_in, const int* in_sizes, int n_in,
                              void* d_out, int out_size)
{
    const float* x    = (const float*)d_in[0];
    const int*   nn   = (const int*)  d_in[1];
    const float* diag = (const float*)d_in[2];
    const float* rot  = (const float*)d_in[3];
    float* out = (float*)d_out;

    prep_kernel<<<NBLK, NTHR>>>(rot, out);
    main_kernel<<<NBLK, NTHR>>>(x, nn, diag, rot, out);
}

// round 5
// speedup vs baseline: 1.3372x; 1.1387x over previous
#include <cuda_runtime.h>

// PowerLinear:
//   c = colsum(R), rs = rowsum(R)
//   n_b == 0 : y_b = (c . x_b) * rs        (handled as sum of chunk-local cxp * rs)
//   n_b >= 1 : y_b = R @ ( d^{n_b} * c * x_b )
// Inputs: x [64,1024] f32, n [64] i32, diag [1024] f32, rot [1024,1024] f32
// Output: [64,1024] f32

#define BB 64
#define DD 1024
#define NP 128            // K1 grid / number of colsum partials
#define NTHR 256
#define KSPLIT 8
#define KCHUNK 128
#define KC 16
#define NSTAGE 8          // KCHUNK / KC
#define PADB 68

__device__ float g_cp[NP * DD];   // colsum partials [p][j]
__device__ float g_rs[DD];        // rowsums

__device__ __forceinline__ void redadd(float* p, float v)
{
    asm volatile("red.global.add.f32 [%0], %1;" :: "l"(p), "f"(v) : "memory");
}

// ---------------------------------------------------------------------------
// K1: colsum partials (8 rows/block) + exact rowsums + zero out
// ---------------------------------------------------------------------------
__global__ __launch_bounds__(NTHR) void prep_kernel(const float* __restrict__ R,
                                                    float* __restrict__ out)
{
    const int bid = blockIdx.x;
    const int tid = threadIdx.x;

    const float* rp = R + (bid * 8) * DD + tid * 4;
    float4 a = make_float4(0.f, 0.f, 0.f, 0.f);
    float rs[8];
#pragma unroll
    for (int r = 0; r < 8; r++) {
        float4 v = *(const float4*)(rp + r * DD);
        a.x += v.x; a.y += v.y; a.z += v.z; a.w += v.w;
        rs[r] = (v.x + v.y) + (v.z + v.w);
    }
    *(float4*)(g_cp + bid * DD + tid * 4) = a;

    __shared__ float srs[8][NTHR];
#pragma unroll
    for (int r = 0; r < 8; r++) srs[r][tid] = rs[r];
    __syncthreads();
#pragma unroll
    for (int off = 128; off > 0; off >>= 1) {
        if (tid < off) {
#pragma unroll
            for (int r = 0; r < 8; r++) srs[r][tid] += srs[r][tid + off];
        }
        __syncthreads();
    }
    if (tid < 8) g_rs[bid * 8 + tid] = srs[tid][0];

    // zero output (64*1024 / 128 blocks = 512 floats per block)
    *(float2*)(out + bid * 512 + tid * 2) = make_float2(0.f, 0.f);
}

// ---------------------------------------------------------------------------
// K2: self-contained split-K GEMM.
// Block (it, ks): i-tile [it*64,+64), k-chunk [ks*128,+128).
//   prologue: c chunk from partials (coalesced), rs tile, build sW from
//             c*diag^n*x (n==0 rows -> 0) + chunk-local cxp.
//   main:     double-buffered R streaming, 4x4 register tiles.
//   epilogue: red.global.add  out += acc + (n0 ? cxp*rs : 0)
// ---------------------------------------------------------------------------
__global__ __launch_bounds__(NTHR, 1)
void gemm_kernel(const float* __restrict__ x,
                 const int*   __restrict__ n,
                 const float* __restrict__ diag,
                 const float* __restrict__ R,
                 float*       __restrict__ out)
{
    __shared__ __align__(16) float sW[KCHUNK][PADB];   // W[k][b]
    __shared__ __align__(16) float sB[2][KC][PADB];    // R[k][i] (transposed tile)
    __shared__ float sm_c[KCHUNK];
    __shared__ float sm_rs[64];
    __shared__ float sm_cxp[64];
    __shared__ int   sm_n0[64];

    const int bid = blockIdx.x;
    const int tid = threadIdx.x;
    const int it  = bid >> 3;
    const int ks  = bid & 7;
    const int i0  = it * 64;
    const int k0  = ks * KCHUNK;

    // ---- prologue: c chunk (coalesced across t), rs tile -------------------
    if (tid < 128) {
        float s = 0.f;
#pragma unroll 16
        for (int p = 0; p < NP; p++) s += g_cp[p * DD + k0 + tid];
        sm_c[tid] = s;
    } else if (tid < 192) {
        sm_rs[tid - 128] = g_rs[i0 + (tid - 128)];
    }
    __syncthreads();

    // ---- build W tile in smem + local cxp ----------------------------------
    {
        const int wb = tid >> 2;          // b 0..63
        const int wq = (tid & 3) * 4;     // k offset quad
        const int nb = n[wb];
        float cxp = 0.f;
#pragma unroll
        for (int m = 0; m < 8; m++) {
            const int kk = wq + 16 * m;
            float4 xv = *(const float4*)(x + wb * DD + k0 + kk);
            float4 dv = *(const float4*)(diag + k0 + kk);
            float xs[4] = {xv.x, xv.y, xv.z, xv.w};
            float ds[4] = {dv.x, dv.y, dv.z, dv.w};
#pragma unroll
            for (int c = 0; c < 4; c++) {
                const float cx = sm_c[kk + c] * xs[c];
                cxp += cx;
                float p = 1.f;
#pragma unroll
                for (int k = 0; k < 5; k++) p *= (k < nb) ? ds[c] : 1.f;
                sW[kk + c][wb] = (nb == 0) ? 0.f : cx * p;
            }
        }
        cxp += __shfl_down_sync(0xffffffffu, cxp, 1, 4);
        cxp += __shfl_down_sync(0xffffffffu, cxp, 2, 4);
        if ((tid & 3) == 0) {
            sm_cxp[wb] = cxp;
            sm_n0[wb]  = (nb == 0);
        }
    }

    // ---- GEMM: stream R tile through double-buffered sB --------------------
    const int tx = tid & 15;
    const int ty = tid >> 4;
    const int li = tid >> 2;            // 0..63 (i row in tile)
    const int lk = (tid & 3) * 4;       // 0,4,8,12

    float acc[4][4];
#pragma unroll
    for (int r = 0; r < 4; r++)
#pragma unroll
        for (int c = 0; c < 4; c++) acc[r][c] = 0.f;

    float4 rr = *(const float4*)(R + (i0 + li) * DD + k0 + lk);
    __syncthreads();   // sW / sm_* ready

    int buf = 0;
#pragma unroll
    for (int s = 0; s < NSTAGE; s++) {
        sB[buf][lk + 0][li] = rr.x;
        sB[buf][lk + 1][li] = rr.y;
        sB[buf][lk + 2][li] = rr.z;
        sB[buf][lk + 3][li] = rr.w;
        __syncthreads();

        if (s + 1 < NSTAGE) {
            const int kb = k0 + (s + 1) * KC;
            rr = *(const float4*)(R + (i0 + li) * DD + kb + lk);
        }

#pragma unroll
        for (int kk = 0; kk < KC; kk++) {
            const float4 av = *(const float4*)&sW[s * KC + kk][ty * 4];
            const float4 bv = *(const float4*)&sB[buf][kk][tx * 4];
            acc[0][0] = fmaf(av.x, bv.x, acc[0][0]);
            acc[0][1] = fmaf(av.x, bv.y, acc[0][1]);
            acc[0][2] = fmaf(av.x, bv.z, acc[0][2]);
            acc[0][3] = fmaf(av.x, bv.w, acc[0][3]);
            acc[1][0] = fmaf(av.y, bv.x, acc[1][0]);
            acc[1][1] = fmaf(av.y, bv.y, acc[1][1]);
            acc[1][2] = fmaf(av.y, bv.z, acc[1][2]);
            acc[1][3] = fmaf(av.y, bv.w, acc[1][3]);
            acc[2][0] = fmaf(av.z, bv.x, acc[2][0]);
            acc[2][1] = fmaf(av.z, bv.y, acc[2][1]);
            acc[2][2] = fmaf(av.z, bv.z, acc[2][2]);
            acc[2][3] = fmaf(av.z, bv.w, acc[2][3]);
            acc[3][0] = fmaf(av.w, bv.x, acc[3][0]);
            acc[3][1] = fmaf(av.w, bv.y, acc[3][1]);
            acc[3][2] = fmaf(av.w, bv.z, acc[3][2]);
            acc[3][3] = fmaf(av.w, bv.w, acc[3][3]);
        }
        buf ^= 1;
    }

    // ---- epilogue: atomic accumulate + chunk-local n==0 rank-1 term --------
#pragma unroll
    for (int r = 0; r < 4; r++) {
        const int b = ty * 4 + r;
        const float ex = sm_n0[b] ? sm_cxp[b] : 0.f;
#pragma unroll
        for (int c = 0; c < 4; c++) {
            const int i = tx * 4 + c;
            redadd(out + b * DD + i0 + i, acc[r][c] + ex * sm_rs[i]);
        }
    }
}

// ---------------------------------------------------------------------------
extern "C" void kernel_launch(void* const* d_in, const int* in_sizes, int n_in,
                              void* d_out, int out_size)
{
    const float* x    = (const float*)d_in[0];
    const int*   nn   = (const int*)  d_in[1];
    const float* diag = (const float*)d_in[2];
    const float* rot  = (const float*)d_in[3];
    float* out = (float*)d_out;

    prep_kernel<<<NP, NTHR>>>(rot, out);
    gemm_kernel<<<128, NTHR>>>(x, nn, diag, rot, out);
}

// round 6
// speedup vs baseline: 1.4797x; 1.1066x over previous
#include <cuda_runtime.h>

// PowerLinear:
//   c = colsum(R), rs = rowsum(R)
//   n_b == 0 : y_b = (c . x_b) * rs     (sum of chunk-local cxp * rs over ks)
//   n_b >= 1 : y_b = R @ ( d^{n_b} * c * x_b )
// Inputs: x [64,1024] f32, n [64] i32, diag [1024] f32, rot [1024,1024] f32
// Output: [64,1024] f32

#define BB 64
#define DD 1024
#define NP 128            // colsum partial count (prep grid)
#define NTHR 256
#define KSPLIT 16
#define KCHUNK 64         // DD / KSPLIT
#define KC 16
#define NSTAGE 4          // KCHUNK / KC
#define PADB 68

__device__ float g_cp[NP * DD];   // colsum partials [p][j]
__device__ float g_rs[DD];        // rowsums

__device__ __forceinline__ void redadd2(float* p, float a, float b)
{
    asm volatile("red.global.add.v2.f32 [%0], {%1, %2};"
                 :: "l"(p), "f"(a), "f"(b) : "memory");
}

// ---------------------------------------------------------------------------
// K1: colsum partials (8 rows/block) + exact rowsums + zero out
// ---------------------------------------------------------------------------
__global__ __launch_bounds__(NTHR) void prep_kernel(const float* __restrict__ R,
                                                    float* __restrict__ out)
{
    const int bid = blockIdx.x;
    const int tid = threadIdx.x;

    const float* rp = R + (bid * 8) * DD + tid * 4;
    float4 a = make_float4(0.f, 0.f, 0.f, 0.f);
    float rs[8];
#pragma unroll
    for (int r = 0; r < 8; r++) {
        float4 v = *(const float4*)(rp + r * DD);
        a.x += v.x; a.y += v.y; a.z += v.z; a.w += v.w;
        rs[r] = (v.x + v.y) + (v.z + v.w);
    }
    *(float4*)(g_cp + bid * DD + tid * 4) = a;

    __shared__ float srs[8][NTHR];
#pragma unroll
    for (int r = 0; r < 8; r++) srs[r][tid] = rs[r];
    __syncthreads();
#pragma unroll
    for (int off = 128; off > 0; off >>= 1) {
        if (tid < off) {
#pragma unroll
            for (int r = 0; r < 8; r++) srs[r][tid] += srs[r][tid + off];
        }
        __syncthreads();
    }
    if (tid < 8) g_rs[bid * 8 + tid] = srs[tid][0];

    // zero output (64*1024 / 128 blocks = 512 floats per block)
    *(float2*)(out + bid * 512 + tid * 2) = make_float2(0.f, 0.f);
}

// ---------------------------------------------------------------------------
// K2: self-contained split-K GEMM, 2 blocks/SM.
// Block (it, ks): i-tile [it*64,+64), k-chunk [ks*64,+64).
// ---------------------------------------------------------------------------
__global__ __launch_bounds__(NTHR, 2)
void gemm_kernel(const float* __restrict__ x,
                 const int*   __restrict__ n,
                 const float* __restrict__ diag,
                 const float* __restrict__ R,
                 float*       __restrict__ out)
{
    __shared__ __align__(16) float sW[KCHUNK][PADB];   // W[k][b]
    __shared__ __align__(16) float sB[2][KC][PADB];    // R[k][i] transposed tile
    __shared__ float sm_cred[4][KCHUNK];
    __shared__ float sm_c[KCHUNK];
    __shared__ float sm_rs[64];
    __shared__ float sm_cxp[64];
    __shared__ int   sm_n0[64];

    const int bid = blockIdx.x;
    const int tid = threadIdx.x;
    const int it  = bid >> 4;           // 0..15
    const int ks  = bid & 15;           // 0..15
    const int i0  = it * 64;
    const int k0  = ks * KCHUNK;

    // ---- prologue: c chunk (4-way split over partials), rs tile ------------
    {
        const int col = tid & 63;
        const int ph  = tid >> 6;       // 0..3
        float s = 0.f;
#pragma unroll 16
        for (int p = ph * 32; p < ph * 32 + 32; p++)
            s += g_cp[p * DD + k0 + col];
        sm_cred[ph][col] = s;
    }
    if (tid >= 192) sm_rs[tid - 192] = g_rs[i0 + (tid - 192)];
    __syncthreads();
    if (tid < KCHUNK)
        sm_c[tid] = (sm_cred[0][tid] + sm_cred[1][tid]) +
                    (sm_cred[2][tid] + sm_cred[3][tid]);
    __syncthreads();

    // ---- build W tile in smem + chunk-local cxp ----------------------------
    {
        const int wb = tid >> 2;          // b 0..63
        const int wq = (tid & 3) * 4;     // k offset quad
        const int nb = n[wb];
        float cxp = 0.f;
#pragma unroll
        for (int m = 0; m < 4; m++) {
            const int kk = wq + 16 * m;
            float4 xv = *(const float4*)(x + wb * DD + k0 + kk);
            float4 dv = *(const float4*)(diag + k0 + kk);
            float xs[4] = {xv.x, xv.y, xv.z, xv.w};
            float ds[4] = {dv.x, dv.y, dv.z, dv.w};
#pragma unroll
            for (int c = 0; c < 4; c++) {
                const float cx = sm_c[kk + c] * xs[c];
                cxp += cx;
                float p = 1.f;
#pragma unroll
                for (int k = 0; k < 5; k++) p *= (k < nb) ? ds[c] : 1.f;
                sW[kk + c][wb] = (nb == 0) ? 0.f : cx * p;
            }
        }
        cxp += __shfl_down_sync(0xffffffffu, cxp, 1, 4);
        cxp += __shfl_down_sync(0xffffffffu, cxp, 2, 4);
        if ((tid & 3) == 0) {
            sm_cxp[wb] = cxp;
            sm_n0[wb]  = (nb == 0);
        }
    }

    // ---- GEMM: stream R tile through double-buffered sB --------------------
    const int tx = tid & 15;
    const int ty = tid >> 4;
    const int li = tid >> 2;            // 0..63 (i row in tile)
    const int lk = (tid & 3) * 4;       // 0,4,8,12

    float acc[4][4];
#pragma unroll
    for (int r = 0; r < 4; r++)
#pragma unroll
        for (int c = 0; c < 4; c++) acc[r][c] = 0.f;

    float4 rr = *(const float4*)(R + (i0 + li) * DD + k0 + lk);
    __syncthreads();   // sW / sm_* ready

    int buf = 0;
#pragma unroll
    for (int s = 0; s < NSTAGE; s++) {
        sB[buf][lk + 0][li] = rr.x;
        sB[buf][lk + 1][li] = rr.y;
        sB[buf][lk + 2][li] = rr.z;
        sB[buf][lk + 3][li] = rr.w;
        __syncthreads();

        if (s + 1 < NSTAGE) {
            const int kb = k0 + (s + 1) * KC;
            rr = *(const float4*)(R + (i0 + li) * DD + kb + lk);
        }

#pragma unroll
        for (int kk = 0; kk < KC; kk++) {
            const float4 av = *(const float4*)&sW[s * KC + kk][ty * 4];
            const float4 bv = *(const float4*)&sB[buf][kk][tx * 4];
            acc[0][0] = fmaf(av.x, bv.x, acc[0][0]);
            acc[0][1] = fmaf(av.x, bv.y, acc[0][1]);
            acc[0][2] = fmaf(av.x, bv.z, acc[0][2]);
            acc[0][3] = fmaf(av.x, bv.w, acc[0][3]);
            acc[1][0] = fmaf(av.y, bv.x, acc[1][0]);
            acc[1][1] = fmaf(av.y, bv.y, acc[1][1]);
            acc[1][2] = fmaf(av.y, bv.z, acc[1][2]);
            acc[1][3] = fmaf(av.y, bv.w, acc[1][3]);
            acc[2][0] = fmaf(av.z, bv.x, acc[2][0]);
            acc[2][1] = fmaf(av.z, bv.y, acc[2][1]);
            acc[2][2] = fmaf(av.z, bv.z, acc[2][2]);
            acc[2][3] = fmaf(av.z, bv.w, acc[2][3]);
            acc[3][0] = fmaf(av.w, bv.x, acc[3][0]);
            acc[3][1] = fmaf(av.w, bv.y, acc[3][1]);
            acc[3][2] = fmaf(av.w, bv.z, acc[3][2]);
            acc[3][3] = fmaf(av.w, bv.w, acc[3][3]);
        }
        buf ^= 1;
    }

    // ---- epilogue: vector atomic accumulate + n==0 rank-1 term -------------
#pragma unroll
    for (int r = 0; r < 4; r++) {
        const int b = ty * 4 + r;
        const float ex = sm_n0[b] ? sm_cxp[b] : 0.f;
        float v[4];
#pragma unroll
        for (int c = 0; c < 4; c++)
            v[c] = acc[r][c] + ex * sm_rs[tx * 4 + c];
        float* po = out + b * DD + i0 + tx * 4;
        redadd2(po, v[0], v[1]);
        redadd2(po + 2, v[2], v[3]);
    }
}

// ---------------------------------------------------------------------------
extern "C" void kernel_launch(void* const* d_in, const int* in_sizes, int n_in,
                              void* d_out, int out_size)
{
    const float* x    = (const float*)d_in[0];
    const int*   nn   = (const int*)  d_in[1];
    const float* diag = (const float*)d_in[2];
    const float* rot  = (const float*)d_in[3];
    float* out = (float*)d_out;

    prep_kernel<<<NP, NTHR>>>(rot, out);
    gemm_kernel<<<256, NTHR>>>(x, nn, diag, rot, out);
}